// round 12
// baseline (speedup 1.0000x reference)
#include <cuda_runtime.h>
#include <cuda_fp16.h>
#include <cstdint>

// Problem constants
constexpr int NN   = 50000;
constexpr int DIN  = 128;
constexpr int DOUT = 128;
constexpr int ELLW = 64;

// Scratch
__device__ __half   g_h16[(size_t)NN * DIN];        // fp16 copy of h (12.8 MB)
__device__ __half   g_w16[DIN * DOUT];              // fp16 copy of W (32 KB)
__device__ __half   g_hw[(size_t)NN * DOUT];        // fp16 projected features (12.8 MB)
__device__ uint16_t g_ell[(size_t)NN * ELLW];       // packed src ids (6.4 MB)
__device__ int      g_cnt[NN];                      // zero at every launch entry
                                                    // (zero-init + agg resets)

// m16n8k16 fp16 mma, f32 accumulate: D += A*B
#define MMA_F16(d, a, b)                                                      \
    asm volatile("mma.sync.aligned.m16n8k16.row.col.f32.f16.f16.f32 "         \
        "{%0,%1,%2,%3}, {%4,%5,%6,%7}, {%8,%9}, {%0,%1,%2,%3};"               \
        : "+f"((d)[0]), "+f"((d)[1]), "+f"((d)[2]), "+f"((d)[3])              \
        : "r"((a)[0]), "r"((a)[1]), "r"((a)[2]), "r"((a)[3]),                 \
          "r"((b)[0]), "r"((b)[1]))

#define LDM_X4(r, addr)                                                       \
    asm volatile("ldmatrix.sync.aligned.m8n8.x4.shared.b16 {%0,%1,%2,%3}, [%4];" \
        : "=r"((r)[0]), "=r"((r)[1]), "=r"((r)[2]), "=r"((r)[3]) : "r"(addr))

#define LDM_X4_T(r, addr)                                                     \
    asm volatile("ldmatrix.sync.aligned.m8n8.x4.trans.shared.b16 {%0,%1,%2,%3}, [%4];" \
        : "=r"((r)[0]), "=r"((r)[1]), "=r"((r)[2]), "=r"((r)[3]) : "r"(addr))

#define CP_ASYNC16(dst, src)                                                  \
    asm volatile("cp.async.ca.shared.global [%0], [%1], 16;"                  \
        :: "r"(dst), "l"(src) : "memory")
#define CP_COMMIT()  asm volatile("cp.async.commit_group;" ::: "memory")
#define CP_WAIT0()   asm volatile("cp.async.wait_group 0;" ::: "memory")

__device__ __forceinline__ __half2 H2(uint32_t u) { return *(__half2*)&u; }

// Pitch 136 halves = 272 B = 17 quads -> conflict-free ldmatrix phases,
// 16B-aligned rows for cp.async.
constexpr int PIT = 136;                        // halves
constexpr int A_HALVES = 64 * PIT;              // 8704  (17,408 B)
constexpr int W_HALVES = 128 * PIT;             // 17408 (34,816 B)
constexpr int SMEM_BYTES = (A_HALVES + W_HALVES) * 2;   // 52,224 B

// fused prep/build grid split
constexpr int NB_BUILD = (800000 + 255) / 256;  // upper bound; real E checked
constexpr int NB_W     = 16;                    // 16*256*4 = 16384 = DIN*DOUT
constexpr int NB_H     = (NN * DIN / 4 + 255) / 256;   // 6250

// ---------------------------------------------------------------------------
// Kernel A (fused): build ELL adjacency (blocks [0, nbuild)), convert W
// (next 16 blocks), convert h (rest). All independent; build is
// atomic-latency-bound and overlaps the BW-bound conversions.
// Requires g_cnt == 0 on entry (initial zero-init; agg_kernel resets).
// ---------------------------------------------------------------------------
__global__ void __launch_bounds__(256) prep_build_kernel(
    const float* __restrict__ h,
    const float* __restrict__ W,
    const int*   __restrict__ src,
    const int*   __restrict__ dst,
    int E, int nbuild)
{
    const int tid = threadIdx.x;
    const int b   = blockIdx.x;

    if (b < nbuild) {
        int e = b * 256 + tid;
        if (e < E) {
            int s = __ldg(src + e);
            int d = __ldg(dst + e);
            int pos = atomicAdd(&g_cnt[d], 1);
            if (pos < ELLW)   // deg > 64: P ~ 1e-13 with Poisson(16) degrees
                g_ell[(size_t)d * ELLW + pos] = (uint16_t)s;
        }
        return;
    }
    if (b < nbuild + NB_W) {
        int i = (b - nbuild) * 256 + tid;
        if (i < DIN * DOUT / 4) {
            float4 v = *(const float4*)(W + (size_t)i * 4);
            __half hh[4] = {__float2half_rn(v.x), __float2half_rn(v.y),
                            __float2half_rn(v.z), __float2half_rn(v.w)};
            *(uint2*)(g_w16 + (size_t)i * 4) = *(uint2*)hh;
        }
        return;
    }
    {
        int i = (b - nbuild - NB_W) * 256 + tid;
        if (i < NN * DIN / 4) {
            float4 v = *(const float4*)(h + (size_t)i * 4);
            __half hh[4] = {__float2half_rn(v.x), __float2half_rn(v.y),
                            __float2half_rn(v.z), __float2half_rn(v.w)};
            *(uint2*)(g_h16 + (size_t)i * 4) = *(uint2*)hh;
        }
    }
}

// ---------------------------------------------------------------------------
// Kernel B: hw = fp16((h @ W) * norm), single fp16 mma (f32 accum).
// CTA: 64 rows x 128 cols, 4 warps (warp tile 32x64), full K=128 resident.
// Fills via cp.async from pre-converted fp16 globals.
// ---------------------------------------------------------------------------
__global__ void __launch_bounds__(128, 4) gemm_mma_kernel(
    const float* __restrict__ norm)
{
    extern __shared__ __half smem_h[];

    const int tid  = threadIdx.x;
    const int lane = tid & 31;
    const int wid  = tid >> 5;
    const int wm   = wid & 1;                   // m block (32 rows)
    const int wn   = wid >> 1;                  // n block (64 cols)
    const int g    = lane >> 2;
    const int t    = lane & 3;
    const int row0 = blockIdx.x * 64;

    const uint32_t sb = (uint32_t)__cvta_generic_to_shared(smem_h);
    const uint32_t sA = sb;                      // As: [64 r][PIT k]
    const uint32_t sW = sb + A_HALVES * 2;       // Ws: [128 k][PIT n] (K-major)

    // ---- async fills: A = 1024 16B-granules, W = 2048 ----
    #pragma unroll
    for (int it = 0; it < 8; it++) {
        int i  = it * 128 + tid;
        int r  = i >> 4;
        int gq = (i & 15) << 3;
        int gr = row0 + r;
        if (gr >= NN) gr = NN - 1;               // clamp (stores guarded later)
        CP_ASYNC16(sA + (uint32_t)(r * PIT + gq) * 2,
                   g_h16 + (size_t)gr * DIN + gq);
    }
    #pragma unroll
    for (int it = 0; it < 16; it++) {
        int i  = it * 128 + tid;
        int k  = i >> 4;
        int gq = (i & 15) << 3;
        CP_ASYNC16(sW + (uint32_t)(k * PIT + gq) * 2,
                   g_w16 + (size_t)k * DOUT + gq);
    }
    CP_COMMIT();
    CP_WAIT0();
    __syncthreads();

    const uint32_t adrA = sA + (uint32_t)(((wm * 32 + (lane & 15)) * PIT
                                           + ((lane >> 4) << 3)) * 2);
    const uint32_t adrB = sW + (uint32_t)(((lane & 15) * PIT
                                           + wn * 64 + ((lane >> 4) << 3)) * 2);

    float acc[2][8][4];
    #pragma unroll
    for (int mt = 0; mt < 2; mt++)
        #pragma unroll
        for (int nt = 0; nt < 8; nt++)
            #pragma unroll
            for (int e = 0; e < 4; e++)
                acc[mt][nt][e] = 0.f;

    #pragma unroll
    for (int ks = 0; ks < 8; ks++) {
        const uint32_t akb = (uint32_t)(ks * 16 * 2);
        const uint32_t bkb = (uint32_t)(ks * 16 * PIT * 2);

        uint32_t ah[2][4];
        #pragma unroll
        for (int mt = 0; mt < 2; mt++)
            LDM_X4(ah[mt], adrA + (uint32_t)(mt * 16 * PIT * 2) + akb);

        #pragma unroll
        for (int np = 0; np < 4; np++) {
            uint32_t bv[4];
            LDM_X4_T(bv, adrB + (uint32_t)(np * 16 * 2) + bkb);
            #pragma unroll
            for (int half = 0; half < 2; half++) {
                int nt = 2 * np + half;
                uint32_t b[2] = {bv[2 * half], bv[2 * half + 1]};
                #pragma unroll
                for (int mt = 0; mt < 2; mt++)
                    MMA_F16(acc[mt][nt], ah[mt], b);
            }
        }
    }

    // ---- epilogue: scale by norm[row], convert to fp16, store g_hw ----
    #pragma unroll
    for (int mt = 0; mt < 2; mt++) {
        int r_lo = row0 + wm * 32 + mt * 16 + g;
        int r_hi = r_lo + 8;
        float n_lo = (r_lo < NN) ? __ldg(norm + r_lo) : 0.f;
        float n_hi = (r_hi < NN) ? __ldg(norm + r_hi) : 0.f;
        #pragma unroll
        for (int nt = 0; nt < 8; nt++) {
            int col = wn * 64 + nt * 8 + 2 * t;
            if (r_lo < NN) {
                __half2 o = __floats2half2_rn(acc[mt][nt][0] * n_lo,
                                              acc[mt][nt][1] * n_lo);
                *(__half2*)(g_hw + (size_t)r_lo * DOUT + col) = o;
            }
            if (r_hi < NN) {
                __half2 o = __floats2half2_rn(acc[mt][nt][2] * n_hi,
                                              acc[mt][nt][3] * n_hi);
                *(__half2*)(g_hw + (size_t)r_hi * DOUT + col) = o;
            }
        }
    }
}

// ---------------------------------------------------------------------------
// Kernel C: aggregate + fused epilogue. One warp per dst node.
// Half-warp scheme: half 0 takes even neighbor slots, half 1 odd; each lane
// loads 16B (8 cols). Depth-2 fp16 tree per 4 rows (per half), fp32 master
// accumulator, butterfly merge across halves. Resets g_cnt for next launch.
// ---------------------------------------------------------------------------
__global__ void __launch_bounds__(256) agg_kernel(
    float* __restrict__ out,
    const float* __restrict__ norm,
    const float* __restrict__ bias)
{
    int warp = (blockIdx.x * blockDim.x + threadIdx.x) >> 5;
    int lane = threadIdx.x & 31;
    if (warp >= NN) return;
    const int d    = warp;
    const int half = lane >> 4;
    const int cl   = lane & 15;          // col group: halves [8cl, 8cl+8)

    int cnt_raw = __ldg(&g_cnt[d]);
    int n = cnt_raw < ELLW ? cnt_raw : ELLW;
    if (lane == 0) g_cnt[d] = 0;         // reset for next launch/replay

    // lane i holds packed ids for slots 2i, 2i+1
    uint32_t packed = *(const uint32_t*)(g_ell + (size_t)d * ELLW + 2 * lane);

    float acc[8];
    #pragma unroll
    for (int j = 0; j < 8; j++) acc[j] = 0.f;

    const __half* base = g_hw + cl * 8;

    int i = 0;
    // 8 rows per iteration: this half handles 4 (even or odd slots)
    for (; i + 8 <= n; i += 8) {
        uint32_t p0 = __shfl_sync(0xffffffffu, packed, (i >> 1) + 0);
        uint32_t p1 = __shfl_sync(0xffffffffu, packed, (i >> 1) + 1);
        uint32_t p2 = __shfl_sync(0xffffffffu, packed, (i >> 1) + 2);
        uint32_t p3 = __shfl_sync(0xffffffffu, packed, (i >> 1) + 3);
        int sa = (int)(half ? (p0 >> 16) : (p0 & 0xffffu));
        int sb = (int)(half ? (p1 >> 16) : (p1 & 0xffffu));
        int sc = (int)(half ? (p2 >> 16) : (p2 & 0xffffu));
        int sd = (int)(half ? (p3 >> 16) : (p3 & 0xffffu));

        uint4 ua = *(const uint4*)(base + (size_t)sa * DOUT);
        uint4 ub = *(const uint4*)(base + (size_t)sb * DOUT);
        uint4 uc = *(const uint4*)(base + (size_t)sc * DOUT);
        uint4 ud = *(const uint4*)(base + (size_t)sd * DOUT);

        // depth-2 fp16 tree (same depth as round 11 -> same noise)
        __half2 s0 = __hadd2(__hadd2(H2(ua.x), H2(ub.x)), __hadd2(H2(uc.x), H2(ud.x)));
        __half2 s1 = __hadd2(__hadd2(H2(ua.y), H2(ub.y)), __hadd2(H2(uc.y), H2(ud.y)));
        __half2 s2 = __hadd2(__hadd2(H2(ua.z), H2(ub.z)), __hadd2(H2(uc.z), H2(ud.z)));
        __half2 s3 = __hadd2(__hadd2(H2(ua.w), H2(ub.w)), __hadd2(H2(uc.w), H2(ud.w)));

        float2 f0 = __half22float2(s0);
        float2 f1 = __half22float2(s1);
        float2 f2 = __half22float2(s2);
        float2 f3 = __half22float2(s3);
        acc[0] += f0.x; acc[1] += f0.y; acc[2] += f1.x; acc[3] += f1.y;
        acc[4] += f2.x; acc[5] += f2.y; acc[6] += f3.x; acc[7] += f3.y;
    }
    // remainder: 2 rows per step (one per half), exact fp32 accumulation
    for (; i < n; i += 2) {
        uint32_t p = __shfl_sync(0xffffffffu, packed, i >> 1);
        int s = (int)(half ? (p >> 16) : (p & 0xffffu));
        if (i + half < n) {
            uint4 u = *(const uint4*)(base + (size_t)s * DOUT);
            float2 f0 = __half22float2(H2(u.x));
            float2 f1 = __half22float2(H2(u.y));
            float2 f2 = __half22float2(H2(u.z));
            float2 f3 = __half22float2(H2(u.w));
            acc[0] += f0.x; acc[1] += f0.y; acc[2] += f1.x; acc[3] += f1.y;
            acc[4] += f2.x; acc[5] += f2.y; acc[6] += f3.x; acc[7] += f3.y;
        }
    }

    // merge halves (lane l <-> l^16 hold same columns)
    #pragma unroll
    for (int j = 0; j < 8; j++)
        acc[j] += __shfl_xor_sync(0xffffffffu, acc[j], 16);

    if (half == 0) {
        float nr = __ldg(norm + d);
        const float* bp = bias + cl * 8;
        float4 b0 = *(const float4*)(bp);
        float4 b1 = *(const float4*)(bp + 4);
        float4 r0, r1;
        r0.x = fmaxf(fmaf(acc[0], nr, b0.x), 0.f);
        r0.y = fmaxf(fmaf(acc[1], nr, b0.y), 0.f);
        r0.z = fmaxf(fmaf(acc[2], nr, b0.z), 0.f);
        r0.w = fmaxf(fmaf(acc[3], nr, b0.w), 0.f);
        r1.x = fmaxf(fmaf(acc[4], nr, b1.x), 0.f);
        r1.y = fmaxf(fmaf(acc[5], nr, b1.y), 0.f);
        r1.z = fmaxf(fmaf(acc[6], nr, b1.z), 0.f);
        r1.w = fmaxf(fmaf(acc[7], nr, b1.w), 0.f);
        float* op = out + (size_t)d * DOUT + cl * 8;
        *(float4*)(op)     = r0;
        *(float4*)(op + 4) = r1;
    }
}

// ---------------------------------------------------------------------------
// Launch. Input order (metadata): h, weight, bias, norm, src, dst
// ---------------------------------------------------------------------------
extern "C" void kernel_launch(void* const* d_in, const int* in_sizes, int n_in,
                              void* d_out, int out_size)
{
    const float* h    = (const float*)d_in[0];
    const float* W    = (const float*)d_in[1];
    const float* bias = (const float*)d_in[2];
    const float* norm = (const float*)d_in[3];
    const int*   src  = (const int*)d_in[4];
    const int*   dst  = (const int*)d_in[5];
    float*       out  = (float*)d_out;

    const int E = in_sizes[4];

    cudaFuncSetAttribute(gemm_mma_kernel,
                         cudaFuncAttributeMaxDynamicSharedMemorySize, SMEM_BYTES);

    // A) fused: ELL build + h/W fp16 conversion
    {
        int nbuild = (E + 255) / 256;
        prep_build_kernel<<<nbuild + NB_W + NB_H, 256>>>(h, W, src, dst, E, nbuild);
    }

    // B) projection -> fp16 g_hw (cp.async fills + fp16 mma)
    gemm_mma_kernel<<<(NN + 63) / 64, 128, SMEM_BYTES>>>(norm);

    // C) gather-aggregate + fused norm/bias/relu (one warp per node)
    agg_kernel<<<(NN * 32 + 255) / 256, 256>>>(out, norm, bias);
}

// round 13
// speedup vs baseline: 2.6248x; 2.6248x over previous
#include <cuda_runtime.h>
#include <cuda_fp16.h>
#include <cstdint>

// Problem constants
constexpr int NN   = 50000;
constexpr int DIN  = 128;
constexpr int DOUT = 128;
constexpr int ELLW = 64;

// Scratch
__device__ __half   g_h16[(size_t)NN * DIN];        // fp16 copy of h (12.8 MB)
__device__ __half   g_w16[DIN * DOUT];              // fp16 copy of W (32 KB)
__device__ __half   g_hw[(size_t)NN * DOUT];        // fp16 projected features (12.8 MB)
__device__ uint16_t g_ell[(size_t)NN * ELLW];       // packed src ids (6.4 MB)
__device__ int      g_cnt[NN];

// m16n8k16 fp16 mma, f32 accumulate: D += A*B
#define MMA_F16(d, a, b)                                                      \
    asm volatile("mma.sync.aligned.m16n8k16.row.col.f32.f16.f16.f32 "         \
        "{%0,%1,%2,%3}, {%4,%5,%6,%7}, {%8,%9}, {%0,%1,%2,%3};"               \
        : "+f"((d)[0]), "+f"((d)[1]), "+f"((d)[2]), "+f"((d)[3])              \
        : "r"((a)[0]), "r"((a)[1]), "r"((a)[2]), "r"((a)[3]),                 \
          "r"((b)[0]), "r"((b)[1]))

#define LDM_X4(r, addr)                                                       \
    asm volatile("ldmatrix.sync.aligned.m8n8.x4.shared.b16 {%0,%1,%2,%3}, [%4];" \
        : "=r"((r)[0]), "=r"((r)[1]), "=r"((r)[2]), "=r"((r)[3]) : "r"(addr))

#define LDM_X4_T(r, addr)                                                     \
    asm volatile("ldmatrix.sync.aligned.m8n8.x4.trans.shared.b16 {%0,%1,%2,%3}, [%4];" \
        : "=r"((r)[0]), "=r"((r)[1]), "=r"((r)[2]), "=r"((r)[3]) : "r"(addr))

#define CP_ASYNC16(dst, src)                                                  \
    asm volatile("cp.async.ca.shared.global [%0], [%1], 16;"                  \
        :: "r"(dst), "l"(src) : "memory")
#define CP_COMMIT()  asm volatile("cp.async.commit_group;" ::: "memory")
#define CP_WAIT0()   asm volatile("cp.async.wait_group 0;" ::: "memory")

// Pitch 136 halves = 272 B = 17 quads -> conflict-free ldmatrix phases,
// 16B-aligned rows for cp.async.
constexpr int PIT = 136;                        // halves
constexpr int A_HALVES = 128 * PIT;             // 17408 (34,816 B)
constexpr int W_HALVES = 128 * PIT;             // 17408 (34,816 B)
constexpr int SMEM_BYTES = (A_HALVES + W_HALVES) * 2;   // 69,632 B

// ---------------------------------------------------------------------------
// Kernel 0: prep — convert h and W to fp16 globals, zero g_cnt.
// ---------------------------------------------------------------------------
__global__ void __launch_bounds__(256) prep_kernel(
    const float* __restrict__ h,
    const float* __restrict__ W)
{
    int i = blockIdx.x * blockDim.x + threadIdx.x;

    if (i < NN * DIN / 4) {
        float4 v = *(const float4*)(h + (size_t)i * 4);
        __half hh[4] = {__float2half_rn(v.x), __float2half_rn(v.y),
                        __float2half_rn(v.z), __float2half_rn(v.w)};
        *(uint2*)(g_h16 + (size_t)i * 4) = *(uint2*)hh;
    }
    if (i < DIN * DOUT / 4) {
        float4 v = *(const float4*)(W + (size_t)i * 4);
        __half hh[4] = {__float2half_rn(v.x), __float2half_rn(v.y),
                        __float2half_rn(v.z), __float2half_rn(v.w)};
        *(uint2*)(g_w16 + (size_t)i * 4) = *(uint2*)hh;
    }
    if (i < NN) g_cnt[i] = 0;
}

// ---------------------------------------------------------------------------
// Kernel 1: hw = fp16((h @ W) * norm), single fp16 mma (f32 accum).
// CTA: 128 rows x 128 cols, 8 warps (warp tile 32x64), full K=128 resident.
// Fills via cp.async from pre-converted fp16 globals.
// ---------------------------------------------------------------------------
__global__ void __launch_bounds__(256, 2) gemm_mma_kernel(
    const float* __restrict__ norm)
{
    extern __shared__ __half smem_h[];

    const int tid  = threadIdx.x;
    const int lane = tid & 31;
    const int wid  = tid >> 5;
    const int wm   = wid & 3;                   // m block (32 rows, 4 blocks)
    const int wn   = wid >> 2;                  // n block (64 cols, 2 blocks)
    const int g    = lane >> 2;
    const int t    = lane & 3;
    const int row0 = blockIdx.x * 128;

    const uint32_t sb = (uint32_t)__cvta_generic_to_shared(smem_h);
    const uint32_t sA = sb;                      // As: [128 r][PIT k]
    const uint32_t sW = sb + A_HALVES * 2;       // Ws: [128 k][PIT n] (K-major)

    // ---- async fills: A = 2048 16B-granules, W = 2048 ----
    #pragma unroll
    for (int it = 0; it < 8; it++) {
        int i  = it * 256 + tid;
        int r  = i >> 4;                         // 0..127
        int gq = (i & 15) << 3;                  // half offset within row
        int gr = row0 + r;
        if (gr >= NN) gr = NN - 1;               // clamp (stores guarded later)
        CP_ASYNC16(sA + (uint32_t)(r * PIT + gq) * 2,
                   g_h16 + (size_t)gr * DIN + gq);
    }
    #pragma unroll
    for (int it = 0; it < 8; it++) {
        int i  = it * 256 + tid;
        int k  = i >> 4;                         // 0..127
        int gq = (i & 15) << 3;
        CP_ASYNC16(sW + (uint32_t)(k * PIT + gq) * 2,
                   g_w16 + (size_t)k * DOUT + gq);
    }
    CP_COMMIT();
    CP_WAIT0();
    __syncthreads();

    // ldmatrix base addresses (bytes, shared space)
    const uint32_t adrA = sA + (uint32_t)(((wm * 32 + (lane & 15)) * PIT
                                           + ((lane >> 4) << 3)) * 2);
    const uint32_t adrB = sW + (uint32_t)(((lane & 15) * PIT
                                           + wn * 64 + ((lane >> 4) << 3)) * 2);

    float acc[2][8][4];
    #pragma unroll
    for (int mt = 0; mt < 2; mt++)
        #pragma unroll
        for (int nt = 0; nt < 8; nt++)
            #pragma unroll
            for (int e = 0; e < 4; e++)
                acc[mt][nt][e] = 0.f;

    // ---- 8 k-steps of 16 over full K=128 ----
    #pragma unroll
    for (int ks = 0; ks < 8; ks++) {
        const uint32_t akb = (uint32_t)(ks * 16 * 2);          // A: +16 halves in k
        const uint32_t bkb = (uint32_t)(ks * 16 * PIT * 2);    // B: +16 rows in k

        uint32_t ah[2][4];
        #pragma unroll
        for (int mt = 0; mt < 2; mt++)
            LDM_X4(ah[mt], adrA + (uint32_t)(mt * 16 * PIT * 2) + akb);

        #pragma unroll
        for (int np = 0; np < 4; np++) {
            uint32_t bv[4];
            LDM_X4_T(bv, adrB + (uint32_t)(np * 16 * 2) + bkb);
            #pragma unroll
            for (int half = 0; half < 2; half++) {
                int nt = 2 * np + half;
                uint32_t b[2] = {bv[2 * half], bv[2 * half + 1]};
                #pragma unroll
                for (int mt = 0; mt < 2; mt++)
                    MMA_F16(acc[mt][nt], ah[mt], b);
            }
        }
    }

    // ---- epilogue: scale by norm[row], convert to fp16, store g_hw ----
    // wm covers rows wm*32 + mt*16 + {g, g+8}; wn covers cols wn*64 + nt*8 + 2t
    #pragma unroll
    for (int mt = 0; mt < 2; mt++) {
        int r_lo = row0 + wm * 32 + mt * 16 + g;
        int r_hi = r_lo + 8;
        float n_lo = (r_lo < NN) ? __ldg(norm + r_lo) : 0.f;
        float n_hi = (r_hi < NN) ? __ldg(norm + r_hi) : 0.f;
        #pragma unroll
        for (int nt = 0; nt < 8; nt++) {
            int col = wn * 64 + nt * 8 + 2 * t;
            if (r_lo < NN) {
                __half2 o = __floats2half2_rn(acc[mt][nt][0] * n_lo,
                                              acc[mt][nt][1] * n_lo);
                *(__half2*)(g_hw + (size_t)r_lo * DOUT + col) = o;
            }
            if (r_hi < NN) {
                __half2 o = __floats2half2_rn(acc[mt][nt][2] * n_hi,
                                              acc[mt][nt][3] * n_hi);
                *(__half2*)(g_hw + (size_t)r_hi * DOUT + col) = o;
            }
        }
    }
}

// ---------------------------------------------------------------------------
// Kernel 2: build ELL adjacency (u16 ids). One thread per edge.
// ---------------------------------------------------------------------------
__global__ void __launch_bounds__(256) build_kernel(
    const int* __restrict__ src,
    const int* __restrict__ dst,
    float* __restrict__ out,
    int E)
{
    int e = blockIdx.x * blockDim.x + threadIdx.x;
    if (e >= E) return;
    int s = __ldg(src + e);
    int d = __ldg(dst + e);
    int pos = atomicAdd(&g_cnt[d], 1);
    if (pos < ELLW) {
        g_ell[(size_t)d * ELLW + pos] = (uint16_t)s;
    } else {
        // overflow fallback (statistically never; degrees ~ Poisson(16))
        const __half* hs = g_hw + (size_t)s * DOUT;
        float* po = out + (size_t)d * DOUT;
        for (int j = 0; j < DOUT; j += 2) {
            float2 v = __half22float2(*(const __half2*)(hs + j));
            asm volatile("red.global.add.f32 [%0], %1;" :: "l"(po + j),     "f"(v.x) : "memory");
            asm volatile("red.global.add.f32 [%0], %1;" :: "l"(po + j + 1), "f"(v.y) : "memory");
        }
    }
}

// ---------------------------------------------------------------------------
// Kernel 3: aggregate + fused epilogue. One warp per dst node.
// Quad-wise fp16 tree reduction (6 HADD2 per 4 rows), fp32 master accumulator.
// ---------------------------------------------------------------------------
__global__ void __launch_bounds__(256) agg_kernel(
    float* __restrict__ out,
    const float* __restrict__ norm,
    const float* __restrict__ bias)
{
    int warp = (blockIdx.x * blockDim.x + threadIdx.x) >> 5;
    int lane = threadIdx.x & 31;
    if (warp >= NN) return;
    const int d = warp;

    int cnt_raw = __ldg(&g_cnt[d]);
    int n = cnt_raw < ELLW ? cnt_raw : ELLW;

    // lane i holds packed ids for slots 2i, 2i+1
    uint32_t packed = *(const uint32_t*)(g_ell + (size_t)d * ELLW + 2 * lane);

    float4 acc = make_float4(0.f, 0.f, 0.f, 0.f);
    const int co = lane * 4;

    int i = 0;
    for (; i + 4 <= n; i += 4) {
        // 2 shfls deliver 4 ids (2 packed per lane)
        uint32_t p0 = __shfl_sync(0xffffffffu, packed, i >> 1);
        uint32_t p1 = __shfl_sync(0xffffffffu, packed, (i >> 1) + 1);
        int s0 = (int)(p0 & 0xffffu), s1 = (int)(p0 >> 16);
        int s2 = (int)(p1 & 0xffffu), s3 = (int)(p1 >> 16);

        uint2 u0 = *(const uint2*)(g_hw + (size_t)s0 * DOUT + co);
        uint2 u1 = *(const uint2*)(g_hw + (size_t)s1 * DOUT + co);
        uint2 u2 = *(const uint2*)(g_hw + (size_t)s2 * DOUT + co);
        uint2 u3 = *(const uint2*)(g_hw + (size_t)s3 * DOUT + co);

        // fp16 pairwise tree: 4 rows -> 1 (noise ~2e-4 rel)
        __half2 x01 = __hadd2(*(__half2*)&u0.x, *(__half2*)&u1.x);
        __half2 x23 = __hadd2(*(__half2*)&u2.x, *(__half2*)&u3.x);
        __half2 xs  = __hadd2(x01, x23);
        __half2 y01 = __hadd2(*(__half2*)&u0.y, *(__half2*)&u1.y);
        __half2 y23 = __hadd2(*(__half2*)&u2.y, *(__half2*)&u3.y);
        __half2 ys  = __hadd2(y01, y23);

        float2 fx = __half22float2(xs);
        float2 fy = __half22float2(ys);
        acc.x += fx.x; acc.y += fx.y; acc.z += fy.x; acc.w += fy.y;
    }
    // remainder: exact fp32 path
    for (; i < n; i++) {
        uint32_t p = __shfl_sync(0xffffffffu, packed, i >> 1);
        int s0 = (int)((i & 1) ? (p >> 16) : (p & 0xffffu));
        uint2 u = *(const uint2*)(g_hw + (size_t)s0 * DOUT + co);
        float2 a = __half22float2(*(__half2*)&u.x);
        float2 b = __half22float2(*(__half2*)&u.y);
        acc.x += a.x; acc.y += a.y; acc.z += b.x; acc.w += b.y;
    }

    if (cnt_raw > ELLW) {   // never in practice
        float4 ov = *(const float4*)(out + (size_t)d * DOUT + co);
        acc.x += ov.x; acc.y += ov.y; acc.z += ov.z; acc.w += ov.w;
    }

    float nr = __ldg(norm + d);
    float4 b = *(const float4*)(bias + co);
    float4 r;
    r.x = fmaxf(fmaf(acc.x, nr, b.x), 0.f);
    r.y = fmaxf(fmaf(acc.y, nr, b.y), 0.f);
    r.z = fmaxf(fmaf(acc.z, nr, b.z), 0.f);
    r.w = fmaxf(fmaf(acc.w, nr, b.w), 0.f);
    *(float4*)(out + (size_t)d * DOUT + co) = r;
}

// ---------------------------------------------------------------------------
// Launch. Input order (metadata): h, weight, bias, norm, src, dst
// ---------------------------------------------------------------------------
extern "C" void kernel_launch(void* const* d_in, const int* in_sizes, int n_in,
                              void* d_out, int out_size)
{
    const float* h    = (const float*)d_in[0];
    const float* W    = (const float*)d_in[1];
    const float* bias = (const float*)d_in[2];
    const float* norm = (const float*)d_in[3];
    const int*   src  = (const int*)d_in[4];
    const int*   dst  = (const int*)d_in[5];
    float*       out  = (float*)d_out;

    const int E = in_sizes[4];

    cudaFuncSetAttribute(gemm_mma_kernel,
                         cudaFuncAttributeMaxDynamicSharedMemorySize, SMEM_BYTES);

    // 0) convert h, W to fp16 globals; zero g_cnt
    prep_kernel<<<(NN * DIN / 4 + 255) / 256, 256>>>(h, W);

    // 1) projection -> fp16 g_hw (cp.async fills + fp16 mma, 128-row CTAs)
    gemm_mma_kernel<<<(NN + 127) / 128, 256, SMEM_BYTES>>>(norm);

    // 2) build per-dst adjacency (ELL, u16)
    build_kernel<<<(E + 255) / 256, 256>>>(src, dst, out, E);

    // 3) gather-aggregate + fused norm/bias/relu (one warp per node)
    agg_kernel<<<(NN * 32 + 255) / 256, 256>>>(out, norm, bias);
}

// round 14
// speedup vs baseline: 2.7173x; 1.0353x over previous
#include <cuda_runtime.h>
#include <cuda_fp16.h>
#include <cstdint>

// Problem constants
constexpr int NN   = 50000;
constexpr int DIN  = 128;
constexpr int DOUT = 128;
constexpr int ELLW = 64;

// Scratch
__device__ __half   g_w16[DIN * DOUT];              // fp16 copy of W (32 KB)
__device__ __half   g_hw[(size_t)NN * DOUT];        // fp16 projected features (12.8 MB)
__device__ uint16_t g_ell[(size_t)NN * ELLW];       // packed src ids (6.4 MB)
__device__ int      g_cnt[NN];

// m16n8k16 fp16 mma, f32 accumulate: D += A*B
#define MMA_F16(d, a, b)                                                      \
    asm volatile("mma.sync.aligned.m16n8k16.row.col.f32.f16.f16.f32 "         \
        "{%0,%1,%2,%3}, {%4,%5,%6,%7}, {%8,%9}, {%0,%1,%2,%3};"               \
        : "+f"((d)[0]), "+f"((d)[1]), "+f"((d)[2]), "+f"((d)[3])              \
        : "r"((a)[0]), "r"((a)[1]), "r"((a)[2]), "r"((a)[3]),                 \
          "r"((b)[0]), "r"((b)[1]))

#define LDM_X4(r, addr)                                                       \
    asm volatile("ldmatrix.sync.aligned.m8n8.x4.shared.b16 {%0,%1,%2,%3}, [%4];" \
        : "=r"((r)[0]), "=r"((r)[1]), "=r"((r)[2]), "=r"((r)[3]) : "r"(addr))

#define LDM_X4_T(r, addr)                                                     \
    asm volatile("ldmatrix.sync.aligned.m8n8.x4.trans.shared.b16 {%0,%1,%2,%3}, [%4];" \
        : "=r"((r)[0]), "=r"((r)[1]), "=r"((r)[2]), "=r"((r)[3]) : "r"(addr))

#define CP_ASYNC16(dst, src)                                                  \
    asm volatile("cp.async.ca.shared.global [%0], [%1], 16;"                  \
        :: "r"(dst), "l"(src) : "memory")
#define CP_COMMIT()  asm volatile("cp.async.commit_group;" ::: "memory")
#define CP_WAIT0()   asm volatile("cp.async.wait_group 0;" ::: "memory")

// fp16 tile pitch: 136 halves = 272 B = 17 quads -> conflict-free ldmatrix.
constexpr int PIT   = 136;                      // halves
constexpr int PIT32 = 132;                      // fp32 staging pitch (words)

// SMEM layout (bytes)
constexpr int OFF_A32 = 0;                              // [64 r][132 w] fp32
constexpr int A32_B   = 64 * PIT32 * 4;                 // 33,792
constexpr int OFF_A16 = A32_B;                          // [64 r][136 h] fp16
constexpr int A16_B   = 64 * PIT * 2;                   // 17,408
constexpr int OFF_W16 = OFF_A16 + A16_B;                // [128 k][136 h] fp16 (K-major)
constexpr int W16_B   = 128 * PIT * 2;                  // 34,816
constexpr int SMEM_BYTES = OFF_W16 + W16_B;             // 86,016

// ---------------------------------------------------------------------------
// Kernel 0: prep — convert W to fp16 global, zero g_cnt (tiny).
// ---------------------------------------------------------------------------
__global__ void __launch_bounds__(256) prep_kernel(const float* __restrict__ W)
{
    int i = blockIdx.x * blockDim.x + threadIdx.x;
    if (i < DIN * DOUT / 4) {
        float4 v = *(const float4*)(W + (size_t)i * 4);
        __half hh[4] = {__float2half_rn(v.x), __float2half_rn(v.y),
                        __float2half_rn(v.z), __float2half_rn(v.w)};
        *(uint2*)(g_w16 + (size_t)i * 4) = *(uint2*)hh;
    }
    if (i < NN) g_cnt[i] = 0;
}

// ---------------------------------------------------------------------------
// Kernel 1: hw = fp16((h @ W) * norm), single fp16 mma (f32 accum).
// CTA: 64 rows x 128 cols, 4 warps (warp tile 32x64), full K=128 resident.
// h is read as fp32 via cp.async into staging smem, converted in-kernel
// (no fp16 h copy in global memory at all).
// ---------------------------------------------------------------------------
__global__ void __launch_bounds__(128, 2) gemm_mma_kernel(
    const float* __restrict__ h,
    const float* __restrict__ norm)
{
    extern __shared__ char smem[];
    const uint32_t sb   = (uint32_t)__cvta_generic_to_shared(smem);
    const uint32_t sA32 = sb + OFF_A32;
    const uint32_t sA16 = sb + OFF_A16;
    const uint32_t sW16 = sb + OFF_W16;
    float*  A32 = (float*)(smem + OFF_A32);
    __half* A16 = (__half*)(smem + OFF_A16);

    const int tid  = threadIdx.x;
    const int lane = tid & 31;
    const int wid  = tid >> 5;
    const int wm   = wid & 1;                   // m block (32 rows)
    const int wn   = wid >> 1;                  // n block (64 cols)
    const int g    = lane >> 2;
    const int t    = lane & 3;
    const int row0 = blockIdx.x * 64;

    // ---- async fills: A fp32 (2048 granules), W fp16 (2048 granules) ----
    #pragma unroll
    for (int it = 0; it < 16; it++) {
        int i  = it * 128 + tid;
        int r  = i >> 5;                         // 0..63
        int c4 = (i & 31) << 2;                  // float offset (16B granule)
        int gr = row0 + r;
        if (gr >= NN) gr = NN - 1;               // clamp (stores guarded later)
        CP_ASYNC16(sA32 + (uint32_t)(r * PIT32 + c4) * 4,
                   h + (size_t)gr * DIN + c4);
    }
    #pragma unroll
    for (int it = 0; it < 16; it++) {
        int i  = it * 128 + tid;
        int k  = i >> 4;                         // 0..127
        int gq = (i & 15) << 3;                  // half offset
        CP_ASYNC16(sW16 + (uint32_t)(k * PIT + gq) * 2,
                   g_w16 + (size_t)k * DOUT + gq);
    }
    CP_COMMIT();
    CP_WAIT0();
    __syncthreads();

    // ---- convert A fp32 -> fp16 tile (LDS.128 -> cvt -> STS.64) ----
    #pragma unroll
    for (int it = 0; it < 16; it++) {
        int i  = it * 128 + tid;
        int r  = i >> 5;                         // 0..63
        int c4 = (i & 31) << 2;                  // 0..124
        float4 v = *(const float4*)(A32 + r * PIT32 + c4);
        __half2 p0 = __floats2half2_rn(v.x, v.y);
        __half2 p1 = __floats2half2_rn(v.z, v.w);
        __half2* dst2 = (__half2*)(A16 + r * PIT + c4);
        dst2[0] = p0;
        dst2[1] = p1;
    }
    __syncthreads();

    // ldmatrix base addresses (bytes, shared space)
    const uint32_t adrA = sA16 + (uint32_t)(((wm * 32 + (lane & 15)) * PIT
                                             + ((lane >> 4) << 3)) * 2);
    const uint32_t adrB = sW16 + (uint32_t)(((lane & 15) * PIT
                                             + wn * 64 + ((lane >> 4) << 3)) * 2);

    float acc[2][8][4];
    #pragma unroll
    for (int mt = 0; mt < 2; mt++)
        #pragma unroll
        for (int nt = 0; nt < 8; nt++)
            #pragma unroll
            for (int e = 0; e < 4; e++)
                acc[mt][nt][e] = 0.f;

    // ---- 8 k-steps of 16 over full K=128 ----
    #pragma unroll
    for (int ks = 0; ks < 8; ks++) {
        const uint32_t akb = (uint32_t)(ks * 16 * 2);          // A: +16 halves in k
        const uint32_t bkb = (uint32_t)(ks * 16 * PIT * 2);    // B: +16 rows in k

        uint32_t ah[2][4];
        #pragma unroll
        for (int mt = 0; mt < 2; mt++)
            LDM_X4(ah[mt], adrA + (uint32_t)(mt * 16 * PIT * 2) + akb);

        #pragma unroll
        for (int np = 0; np < 4; np++) {
            uint32_t bv[4];
            LDM_X4_T(bv, adrB + (uint32_t)(np * 16 * 2) + bkb);
            #pragma unroll
            for (int half = 0; half < 2; half++) {
                int nt = 2 * np + half;
                uint32_t b[2] = {bv[2 * half], bv[2 * half + 1]};
                #pragma unroll
                for (int mt = 0; mt < 2; mt++)
                    MMA_F16(acc[mt][nt], ah[mt], b);
            }
        }
    }

    // ---- epilogue: scale by norm[row], convert to fp16, store g_hw ----
    #pragma unroll
    for (int mt = 0; mt < 2; mt++) {
        int r_lo = row0 + wm * 32 + mt * 16 + g;
        int r_hi = r_lo + 8;
        float n_lo = (r_lo < NN) ? __ldg(norm + r_lo) : 0.f;
        float n_hi = (r_hi < NN) ? __ldg(norm + r_hi) : 0.f;
        #pragma unroll
        for (int nt = 0; nt < 8; nt++) {
            int col = wn * 64 + nt * 8 + 2 * t;
            if (r_lo < NN) {
                __half2 o = __floats2half2_rn(acc[mt][nt][0] * n_lo,
                                              acc[mt][nt][1] * n_lo);
                *(__half2*)(g_hw + (size_t)r_lo * DOUT + col) = o;
            }
            if (r_hi < NN) {
                __half2 o = __floats2half2_rn(acc[mt][nt][2] * n_hi,
                                              acc[mt][nt][3] * n_hi);
                *(__half2*)(g_hw + (size_t)r_hi * DOUT + col) = o;
            }
        }
    }
}

// ---------------------------------------------------------------------------
// Kernel 2: build ELL adjacency (u16 ids). One thread per edge.
// ---------------------------------------------------------------------------
__global__ void __launch_bounds__(256) build_kernel(
    const int* __restrict__ src,
    const int* __restrict__ dst,
    float* __restrict__ out,
    int E)
{
    int e = blockIdx.x * blockDim.x + threadIdx.x;
    if (e >= E) return;
    int s = __ldg(src + e);
    int d = __ldg(dst + e);
    int pos = atomicAdd(&g_cnt[d], 1);
    if (pos < ELLW) {
        g_ell[(size_t)d * ELLW + pos] = (uint16_t)s;
    } else {
        // overflow fallback (statistically never; degrees ~ Poisson(16))
        const __half* hs = g_hw + (size_t)s * DOUT;
        float* po = out + (size_t)d * DOUT;
        for (int j = 0; j < DOUT; j += 2) {
            float2 v = __half22float2(*(const __half2*)(hs + j));
            asm volatile("red.global.add.f32 [%0], %1;" :: "l"(po + j),     "f"(v.x) : "memory");
            asm volatile("red.global.add.f32 [%0], %1;" :: "l"(po + j + 1), "f"(v.y) : "memory");
        }
    }
}

// ---------------------------------------------------------------------------
// Kernel 3: aggregate + fused epilogue. One warp per dst node.
// Quad-wise fp16 tree reduction (6 HADD2 per 4 rows), fp32 master accumulator.
// ---------------------------------------------------------------------------
__global__ void __launch_bounds__(256) agg_kernel(
    float* __restrict__ out,
    const float* __restrict__ norm,
    const float* __restrict__ bias)
{
    int warp = (blockIdx.x * blockDim.x + threadIdx.x) >> 5;
    int lane = threadIdx.x & 31;
    if (warp >= NN) return;
    const int d = warp;

    int cnt_raw = __ldg(&g_cnt[d]);
    int n = cnt_raw < ELLW ? cnt_raw : ELLW;

    // lane i holds packed ids for slots 2i, 2i+1
    uint32_t packed = *(const uint32_t*)(g_ell + (size_t)d * ELLW + 2 * lane);

    float4 acc = make_float4(0.f, 0.f, 0.f, 0.f);
    const int co = lane * 4;

    int i = 0;
    for (; i + 4 <= n; i += 4) {
        uint32_t p0 = __shfl_sync(0xffffffffu, packed, i >> 1);
        uint32_t p1 = __shfl_sync(0xffffffffu, packed, (i >> 1) + 1);
        int s0 = (int)(p0 & 0xffffu), s1 = (int)(p0 >> 16);
        int s2 = (int)(p1 & 0xffffu), s3 = (int)(p1 >> 16);

        uint2 u0 = *(const uint2*)(g_hw + (size_t)s0 * DOUT + co);
        uint2 u1 = *(const uint2*)(g_hw + (size_t)s1 * DOUT + co);
        uint2 u2 = *(const uint2*)(g_hw + (size_t)s2 * DOUT + co);
        uint2 u3 = *(const uint2*)(g_hw + (size_t)s3 * DOUT + co);

        __half2 x01 = __hadd2(*(__half2*)&u0.x, *(__half2*)&u1.x);
        __half2 x23 = __hadd2(*(__half2*)&u2.x, *(__half2*)&u3.x);
        __half2 xs  = __hadd2(x01, x23);
        __half2 y01 = __hadd2(*(__half2*)&u0.y, *(__half2*)&u1.y);
        __half2 y23 = __hadd2(*(__half2*)&u2.y, *(__half2*)&u3.y);
        __half2 ys  = __hadd2(y01, y23);

        float2 fx = __half22float2(xs);
        float2 fy = __half22float2(ys);
        acc.x += fx.x; acc.y += fx.y; acc.z += fy.x; acc.w += fy.y;
    }
    for (; i < n; i++) {
        uint32_t p = __shfl_sync(0xffffffffu, packed, i >> 1);
        int s0 = (int)((i & 1) ? (p >> 16) : (p & 0xffffu));
        uint2 u = *(const uint2*)(g_hw + (size_t)s0 * DOUT + co);
        float2 a = __half22float2(*(__half2*)&u.x);
        float2 b = __half22float2(*(__half2*)&u.y);
        acc.x += a.x; acc.y += a.y; acc.z += b.x; acc.w += b.y;
    }

    if (cnt_raw > ELLW) {   // never in practice
        float4 ov = *(const float4*)(out + (size_t)d * DOUT + co);
        acc.x += ov.x; acc.y += ov.y; acc.z += ov.z; acc.w += ov.w;
    }

    float nr = __ldg(norm + d);
    float4 b = *(const float4*)(bias + co);
    float4 r;
    r.x = fmaxf(fmaf(acc.x, nr, b.x), 0.f);
    r.y = fmaxf(fmaf(acc.y, nr, b.y), 0.f);
    r.z = fmaxf(fmaf(acc.z, nr, b.z), 0.f);
    r.w = fmaxf(fmaf(acc.w, nr, b.w), 0.f);
    *(float4*)(out + (size_t)d * DOUT + co) = r;
}

// ---------------------------------------------------------------------------
// Launch. Input order (metadata): h, weight, bias, norm, src, dst
// ---------------------------------------------------------------------------
extern "C" void kernel_launch(void* const* d_in, const int* in_sizes, int n_in,
                              void* d_out, int out_size)
{
    const float* h    = (const float*)d_in[0];
    const float* W    = (const float*)d_in[1];
    const float* bias = (const float*)d_in[2];
    const float* norm = (const float*)d_in[3];
    const int*   src  = (const int*)d_in[4];
    const int*   dst  = (const int*)d_in[5];
    float*       out  = (float*)d_out;

    const int E = in_sizes[4];

    cudaFuncSetAttribute(gemm_mma_kernel,
                         cudaFuncAttributeMaxDynamicSharedMemorySize, SMEM_BYTES);

    // 0) convert W to fp16; zero g_cnt (tiny)
    prep_kernel<<<(NN + 255) / 256, 256>>>(W);

    // 1) projection -> fp16 g_hw (cp.async fp32 h + in-smem convert + fp16 mma)
    gemm_mma_kernel<<<(NN + 63) / 64, 128, SMEM_BYTES>>>(h, norm);

    // 2) build per-dst adjacency (ELL, u16)
    build_kernel<<<(E + 255) / 256, 256>>>(src, dst, out, E);

    // 3) gather-aggregate + fused norm/bias/relu (one warp per node)
    agg_kernel<<<(NN * 32 + 255) / 256, 256>>>(out, norm, bias);
}